// round 5
// baseline (speedup 1.0000x reference)
#include <cuda_runtime.h>
#include <math.h>

#define BATCH 2
#define NTOK 256
#define NATOM 2048
#define NTILE 16            // NATOM / 128
#define NPAIRS 136          // NTILE*(NTILE+1)/2
#define GRID (NPAIRS * BATCH)   // 272 blocks
#define NT 256

// ---------------- device scratch (no allocations allowed) ----------------
__device__ double g_acc[BATCH][5];         // bond_num, bond_den, ce, csum, msum
__device__ double g_mom[BATCH][17];        // W, Mask, Swx[3], Swg[3], Sxg[9]
__device__ float4 g_rowx[BATCH][NATOM];    // x0,x1,x2, mask
__device__ float4 g_rowg[BATCH][NATOM];    // g0,g1,g2, isnuc
__device__ float  g_watom[BATCH][NATOM];
__device__ int    g_tok[BATCH][NATOM];
__device__ float  g_S[BATCH][NTOK * NTOK]; // symmetric bond-weight matrix

// sense-reversing grid barrier state (replay-invariant: count self-resets,
// sense flips an even number of times per launch)
__device__ unsigned g_count = 0;
__device__ unsigned g_sense = 0;

__device__ __forceinline__ float sqrt_approx(float v) {
    float y; asm("sqrt.approx.f32 %0, %1;" : "=f"(y) : "f"(v)); return y;
}

__device__ __forceinline__ float det3f(float a00, float a01, float a02,
                                       float a10, float a11, float a12,
                                       float a20, float a21, float a22) {
    return a00*(a11*a22 - a12*a21) - a01*(a10*a22 - a12*a20) + a02*(a10*a21 - a11*a20);
}

// grid-wide barrier; s_sense is block-local (shared), starts at 0 each launch
__device__ __forceinline__ void grid_barrier(unsigned* s_sense) {
    __threadfence();
    __syncthreads();
    if (threadIdx.x == 0) {
        unsigned my = *s_sense ^ 1u;
        unsigned a = atomicAdd(&g_count, 1u);
        if (a == GRID - 1) {
            atomicExch(&g_count, 0u);
            __threadfence();
            atomicExch(&g_sense, my);
        } else {
            while (atomicAdd(&g_sense, 0u) != my) { }
        }
        __threadfence();
        *s_sense = my;
    }
    __syncthreads();
}

__global__ void __launch_bounds__(NT, 2)
fused_kernel(const float* __restrict__ x, const float* __restrict__ gt,
             const float* __restrict__ gmask,
             const float* __restrict__ isp, const float* __restrict__ isd,
             const float* __restrict__ isr, const float* __restrict__ isl,
             const float* __restrict__ tmask, const int* __restrict__ npt,
             const float* __restrict__ tb, const float* __restrict__ t,
             float* __restrict__ out) {
    __shared__ unsigned s_sense;
    int blk = blockIdx.x;
    int tid = threadIdx.x;
    if (tid == 0) s_sense = 0u;

    // =========== Phase 1a: per-batch prep (blocks 0 / 1) ==================
    if (blk < BATCH) {
        int b = blk;
        if (tid == 0) { g_acc[b][0] = 0.0; g_acc[b][2] = 0.0; g_acc[b][3] = 0.0; g_acc[b][4] = 0.0; }

        __shared__ int   cum[NTOK];
        __shared__ float s_nuc[NTOK], s_w[NTOK], s_a[NTOK], s_b[NTOK];

        float tm = tmask[b * NTOK + tid];
        float dv = isd[b * NTOK + tid];
        float rv = isr[b * NTOK + tid];
        float lv = isl[b * NTOK + tid];
        float pv = isp[b * NTOK + tid];

        s_nuc[tid] = (dv + rv) * tm;
        s_w[tid]   = (1.0f + 5.0f * dv + 5.0f * rv + 10.0f * lv) * tm;
        s_a[tid]   = lv * tm;
        s_b[tid]   = (pv + dv + rv) * tm;
        cum[tid]   = npt[b * NTOK + tid];
        __syncthreads();

        for (int off = 1; off < NTOK; off <<= 1) {
            int v = (tid >= off) ? cum[tid - off] : 0;
            __syncthreads();
            cum[tid] += v;
            __syncthreads();
        }
        int total = cum[NTOK - 1];

        const float* xb = x  + (size_t)b * NATOM * 3;
        const float* gb = gt + (size_t)b * NATOM * 3;
        const float* mb = gmask + (size_t)b * NATOM;
        const float* tbb = tb + (size_t)b * NTOK * NTOK;

        double s[18];
        #pragma unroll
        for (int q = 0; q < 18; q++) s[q] = 0.0;

        for (int k = 0; k < NATOM / NTOK; k++) {
            int l = k * NTOK + tid;
            float w_at = 0.f, nuc = 0.f, aL = 0.f, bL = 0.f;
            int tok = 0;
            if (l < total) {
                int lo = 0, hi = NTOK - 1;
                while (lo < hi) {
                    int mid = (lo + hi) >> 1;
                    if (cum[mid] > l) hi = mid; else lo = mid + 1;
                }
                tok = lo; nuc = s_nuc[lo]; w_at = s_w[lo]; aL = s_a[lo]; bL = s_b[lo];
            }
            float mk = mb[l];
            float x0 = xb[3*l+0], x1 = xb[3*l+1], x2 = xb[3*l+2];
            float g0 = gb[3*l+0], g1 = gb[3*l+1], g2 = gb[3*l+2];

            g_rowx[b][l]  = make_float4(x0, x1, x2, mk);
            g_rowg[b][l]  = make_float4(g0, g1, g2, nuc);
            g_watom[b][l] = w_at;
            g_tok[b][l]   = tok;

            double wm = (double)(w_at * mk);
            s[0] += wm; s[1] += (double)mk;
            s[2] += wm*x0; s[3] += wm*x1; s[4] += wm*x2;
            s[5] += wm*g0; s[6] += wm*g1; s[7] += wm*g2;
            s[8]  += wm*x0*g0; s[9]  += wm*x0*g1; s[10] += wm*x0*g2;
            s[11] += wm*x1*g0; s[12] += wm*x1*g1; s[13] += wm*x1*g2;
            s[14] += wm*x2*g0; s[15] += wm*x2*g1; s[16] += wm*x2*g2;
            s[17] += (double)(aL * bL * __ldg(&tbb[tok * NTOK + tok]) * mk * mk);
        }

        __shared__ double red[8][18];
        int lane = tid & 31, w = tid >> 5;
        #pragma unroll
        for (int q = 0; q < 18; q++) {
            double v = s[q];
            for (int off = 16; off > 0; off >>= 1) v += __shfl_xor_sync(0xffffffffu, v, off);
            if (lane == 0) red[w][q] = v;
        }
        __syncthreads();
        if (tid < 17) {
            double v = 0.0;
            #pragma unroll
            for (int ww = 0; ww < 8; ww++) v += red[ww][tid];
            g_mom[b][tid] = v;
        }
        if (tid == 17) {
            double v = 0.0;
            #pragma unroll
            for (int ww = 0; ww < 8; ww++) v += red[ww][17];
            g_acc[b][1] = v;   // bond denominator: diagonal contribution
        }
    }

    // =========== Phase 1b: symmetric S matrix (all blocks) ================
    // S[b][i*NTOK+j] = tb[i,j]*a_i*p_j + tb[j,i]*a_j*p_i
    for (int gid = blk * NT + tid; gid < BATCH * NTOK * NTOK; gid += GRID * NT) {
        int b = gid >> 16;               // / (NTOK*NTOK)
        int ij = gid & 0xFFFF;
        int i = ij >> 8, j = ij & 0xFF;

        float tmi = tmask[b * NTOK + i], tmj = tmask[b * NTOK + j];
        float ai = isl[b*NTOK+i] * tmi;
        float aj = isl[b*NTOK+j] * tmj;
        float pi = (isp[b*NTOK+i] + isd[b*NTOK+i] + isr[b*NTOK+i]) * tmi;
        float pj = (isp[b*NTOK+j] + isd[b*NTOK+j] + isr[b*NTOK+j]) * tmj;

        const float* tbb = tb + (size_t)b * NTOK * NTOK;
        g_S[b][ij] = tbb[i * NTOK + j] * ai * pj + tbb[j * NTOK + i] * aj * pi;
    }

    grid_barrier(&s_sense);

    // =========== Phase 2: triangular pairwise tiles ========================
    {
        int b = blk & 1;
        int p = blk >> 1;
        int I = 0, rem = p;
        while (rem >= (NTILE - I)) { rem -= (NTILE - I); I++; }
        int J = I + rem;

        __shared__ float4 sx0[128], sg0[128], sx1[128], sg1[128];
        __shared__ int    st0[128], st1[128];

        if (tid < 128) {
            int l = I * 128 + tid;
            sx0[tid] = g_rowx[b][l]; sg0[tid] = g_rowg[b][l]; st0[tid] = g_tok[b][l];
        } else {
            int l = J * 128 + (tid - 128);
            sx1[tid-128] = g_rowx[b][l]; sg1[tid-128] = g_rowg[b][l]; st1[tid-128] = g_tok[b][l];
        }
        __syncthreads();

        int r  = tid >> 1;
        int jb = (tid & 1) << 6;
        float4 rx = sx0[r], rg = sg0[r];
        int rS = st0[r] * NTOK;
        const float* Sb = g_S[b];
        bool diag = (I == J);

        const float n1 = 0.846045767f,  n2 = 0.187663961f,  n3 = 0.0091748690f;
        const float d1 = 1.128061023f,  d2 = 0.375327923f,  d3 = 0.036699476f, d4 = 0.00055308437f;

        float a0 = 0.f, a1 = 0.f, a2 = 0.f, a3 = 0.f, a4 = 0.f;

        #pragma unroll 4
        for (int jj = 0; jj < 64; jj++) {
            int j = jb + jj;
            float4 cx = sx1[j], cg = sg1[j];

            float valid = (!diag || (j > r)) ? 1.f : 0.f;
            float pm = rx.w * cx.w * valid;

            float dd0 = rx.x - cx.x, dd1 = rx.y - cx.y, dd2 = rx.z - cx.z;
            float dxv = sqrt_approx(fmaf(dd0, dd0, fmaf(dd1, dd1, fmaf(dd2, dd2, 1e-12f))));

            float ee0 = rg.x - cg.x, ee1 = rg.y - cg.y, ee2 = rg.z - cg.z;
            float dgv = sqrt_approx(fmaf(ee0, ee0, fmaf(ee1, ee1, fmaf(ee2, ee2, 1e-12f))));

            float diff = dxv - dgv;
            float wbs = __ldg(&Sb[rS + st1[j]]) * pm;
            a0 = fmaf(diff * diff, wbs, a0);
            a1 += wbs;

            float d = fminf(fabsf(diff), 20.f);
            float E = __expf(d);
            float num = fmaf(fmaf(fmaf(n3, E, n2), E, n1), E, 1.f);
            float den = fmaf(fmaf(fmaf(fmaf(d4, E, d3), E, d2), E, d1), E, 1.f);
            float e   = __fdividef(num, den);

            float lt15 = (dgv < 15.f) ? 1.f : 0.f;
            float lt30 = (dgv < 30.f) ? 1.f : 0.f;
            float csum = fmaf(rg.w + cg.w, lt30 - lt15, 2.f * lt15) * pm;

            a2 = fmaf(csum, e, a2);
            a3 += csum;
            a4 += 2.f * pm;
        }

        __shared__ float red2[8][5];
        int lane = tid & 31, w = tid >> 5;
        float vals[5] = {a0, a1, a2, a3, a4};
        #pragma unroll
        for (int k = 0; k < 5; k++) {
            float v = vals[k];
            for (int off = 16; off > 0; off >>= 1) v += __shfl_xor_sync(0xffffffffu, v, off);
            if (lane == 0) red2[w][k] = v;
        }
        __syncthreads();
        if (tid < 5) {
            float ssum = 0.f;
            #pragma unroll
            for (int ww = 0; ww < 8; ww++) ssum += red2[ww][tid];
            atomicAdd(&g_acc[b][tid], (double)ssum);
        }
    }

    grid_barrier(&s_sense);

    // =========== Phase 3: QCP Kabsch + MSE + final (block 0) ==============
    if (blk != 0) return;

    __shared__ float sR[BATCH][15];
    __shared__ double sred[8];

    if (tid < BATCH) {
        int b = tid;
        double W = g_mom[b][0];
        double invW = 1.0 / W;
        double sx[3] = {g_mom[b][2], g_mom[b][3], g_mom[b][4]};
        double sg[3] = {g_mom[b][5], g_mom[b][6], g_mom[b][7]};
        double H[3][3];
        for (int i = 0; i < 3; i++)
            for (int j = 0; j < 3; j++)
                H[i][j] = g_mom[b][8 + i * 3 + j] - sx[i] * sg[j] * invW;

        double Sxx = H[0][0], Sxy = H[1][0], Sxz = H[2][0];
        double Syx = H[0][1], Syy = H[1][1], Syz = H[2][1];
        double Szx = H[0][2], Szy = H[1][2], Szz = H[2][2];

        double Nd[4][4] = {
            { Sxx+Syy+Szz,  Syz-Szy,       Szx-Sxz,       Sxy-Syx      },
            { Syz-Szy,      Sxx-Syy-Szz,   Sxy+Syx,       Szx+Sxz      },
            { Szx-Sxz,      Sxy+Syx,      -Sxx+Syy-Szz,   Syz+Szy      },
            { Sxy-Syx,      Szx+Sxz,       Syz+Szy,      -Sxx-Syy+Szz  }};

        double fro = 0.0;
        for (int i = 0; i < 4; i++) for (int j = 0; j < 4; j++) fro += Nd[i][j]*Nd[i][j];
        double scl = 1.0 / sqrt(fro + 1e-300);

        float N[4][4];
        for (int i = 0; i < 4; i++)
            for (int j = 0; j < 4; j++) N[i][j] = (float)(Nd[i][j] * scl);

        float N2[4][4]; float t3 = 0.f, t4 = 0.f;
        #pragma unroll
        for (int i = 0; i < 4; i++)
            #pragma unroll
            for (int j = 0; j < 4; j++) {
                float v = 0.f;
                #pragma unroll
                for (int k = 0; k < 4; k++) v = fmaf(N[i][k], N[k][j], v);
                N2[i][j] = v;
            }
        #pragma unroll
        for (int i = 0; i < 4; i++)
            #pragma unroll
            for (int j = 0; j < 4; j++) {
                t3 = fmaf(N2[i][j], N[i][j], t3);
                t4 = fmaf(N2[i][j], N2[i][j], t4);
            }
        const float a2c = -0.5f;
        float a1c = -t3 * (1.f / 3.f);
        float a0c = 0.125f - 0.25f * t4;

        float lam = 1.0f;
        #pragma unroll
        for (int it = 0; it < 16; it++) {
            float pp = fmaf(fmaf(fmaf(lam, lam, a2c), lam, a1c), lam, a0c);
            float dp = fmaf(fmaf(4.f, lam * lam, 2.f * a2c), lam, a1c);
            lam -= __fdividef(pp, dp);
        }

        float M[4][4];
        for (int i = 0; i < 4; i++)
            for (int j = 0; j < 4; j++) M[i][j] = N[i][j] - ((i == j) ? lam : 0.f);

        float adj[4][4];
        const int rows[4][3] = {{1,2,3},{0,2,3},{0,1,3},{0,1,2}};
        #pragma unroll
        for (int i = 0; i < 4; i++)
            #pragma unroll
            for (int j = 0; j < 4; j++) {
                const int* rr = rows[j];
                const int* cc = rows[i];
                float m3 = det3f(M[rr[0]][cc[0]], M[rr[0]][cc[1]], M[rr[0]][cc[2]],
                                 M[rr[1]][cc[0]], M[rr[1]][cc[1]], M[rr[1]][cc[2]],
                                 M[rr[2]][cc[0]], M[rr[2]][cc[1]], M[rr[2]][cc[2]]);
                adj[i][j] = (((i + j) & 1) ? -m3 : m3);
            }
        int bestc = 0; float bestn = -1.f;
        #pragma unroll
        for (int j = 0; j < 4; j++) {
            float nn = 0.f;
            #pragma unroll
            for (int i = 0; i < 4; i++) nn = fmaf(adj[i][j], adj[i][j], nn);
            if (nn > bestn) { bestn = nn; bestc = j; }
        }
        float qn = __fdividef(1.f, sqrtf(bestn));
        float q0 = adj[0][bestc] * qn, q1 = adj[1][bestc] * qn;
        float q2 = adj[2][bestc] * qn, q3 = adj[3][bestc] * qn;

        float R[3][3] = {
            {1.f-2.f*(q2*q2+q3*q3), 2.f*(q1*q2-q0*q3),     2.f*(q1*q3+q0*q2)},
            {2.f*(q1*q2+q0*q3),     1.f-2.f*(q1*q1+q3*q3), 2.f*(q2*q3-q0*q1)},
            {2.f*(q1*q3-q0*q2),     2.f*(q2*q3+q0*q1),     1.f-2.f*(q1*q1+q2*q2)}};

        float f1 = 0.f, f2 = 0.f;
        for (int i = 0; i < 3; i++)
            for (int j = 0; j < 3; j++) {
                float Hf = (float)(H[i][j] * scl);
                f1 = fmaf(R[i][j], Hf, f1);
                f2 = fmaf(R[j][i], Hf, f2);
            }
        if (f2 > f1) {
            for (int i = 0; i < 3; i++)
                for (int j = i + 1; j < 3; j++) { float tmp = R[i][j]; R[i][j] = R[j][i]; R[j][i] = tmp; }
        }

        for (int i = 0; i < 3; i++)
            for (int j = 0; j < 3; j++) sR[b][i*3+j] = R[i][j];
        for (int i = 0; i < 3; i++) {
            sR[b][9+i]  = (float)(sg[i] * invW);
            sR[b][12+i] = (float)(sx[i] * invW);
        }
    }
    __syncthreads();

    // MSE: threads [0,128) -> batch 0, [128,256) -> batch 1, 16 atoms each
    {
        int b  = tid >> 7;
        int at = tid & 127;

        float R00 = sR[b][0], R01 = sR[b][1], R02 = sR[b][2];
        float R10 = sR[b][3], R11 = sR[b][4], R12 = sR[b][5];
        float R20 = sR[b][6], R21 = sR[b][7], R22 = sR[b][8];
        float mg0 = sR[b][9],  mg1 = sR[b][10], mg2 = sR[b][11];
        float mx0 = sR[b][12], mx1 = sR[b][13], mx2 = sR[b][14];

        double s = 0.0;
        for (int k = 0; k < NATOM / 128; k++) {
            int l = k * 128 + at;
            float4 rx = g_rowx[b][l];
            float4 rg = g_rowg[b][l];
            float g0 = rg.x - mg0, g1 = rg.y - mg1, g2 = rg.z - mg2;
            float c0 = R00*g0 + R01*g1 + R02*g2 + mx0;
            float c1 = R10*g0 + R11*g1 + R12*g2 + mx1;
            float c2 = R20*g0 + R21*g1 + R22*g2 + mx2;
            float e0 = rx.x - c0, e1 = rx.y - c1, e2 = rx.z - c2;
            float e = e0*e0 + e1*e1 + e2*e2;
            s += (double)(e * g_watom[b][l] * rx.w);
        }

        int lane = tid & 31, w = tid >> 5;   // warps 0-3 = b0, 4-7 = b1
        for (int off = 16; off > 0; off >>= 1) s += __shfl_xor_sync(0xffffffffu, s, off);
        if (lane == 0) sred[w] = s;
        __syncthreads();

        if (tid == 0) {
            double loss = 0.0;
            for (int bb = 0; bb < BATCH; bb++) {
                double mse = 0.0;
                for (int ww = 0; ww < 4; ww++) mse += sred[bb * 4 + ww];
                double lbond = g_acc[bb][0] / g_acc[bb][1];
                double ce_m  = g_acc[bb][2] / g_acc[bb][4];
                double c_m   = g_acc[bb][3] / g_acc[bb][4];
                double llddt = 1.0 - ce_m / c_m;
                double lmse  = (mse / g_mom[bb][1]) * (1.0 / 3.0);
                double tv = (double)t[bb];
                double wt = (tv * tv + 256.0) / ((tv + 16.0) * (tv + 16.0));
                loss += wt * (lmse + lbond) + llddt;
            }
            out[0] = (float)(loss / BATCH);
        }
    }
}

// ---------------- launch ---------------------------------------------------
extern "C" void kernel_launch(void* const* d_in, const int* in_sizes, int n_in,
                              void* d_out, int out_size) {
    const float* x   = (const float*)d_in[0];
    const float* gt  = (const float*)d_in[1];
    const float* gm  = (const float*)d_in[2];
    const float* isp = (const float*)d_in[3];
    const float* isd = (const float*)d_in[4];
    const float* isr = (const float*)d_in[5];
    const float* isl = (const float*)d_in[6];
    const float* tb  = (const float*)d_in[7];
    const float* tm  = (const float*)d_in[8];
    const int*   npt = (const int*)d_in[9];
    const float* t   = (const float*)d_in[10];
    float* out = (float*)d_out;

    fused_kernel<<<GRID, NT>>>(x, gt, gm, isp, isd, isr, isl, tm, npt, tb, t, out);
}

// round 6
// speedup vs baseline: 1.0436x; 1.0436x over previous
#include <cuda_runtime.h>
#include <math.h>

#define BATCH 2
#define NTOK 256
#define NATOM 2048
#define NTILE 16                // NATOM / 128
#define NPAIRS 136              // NTILE*(NTILE+1)/2
#define GRID (NPAIRS * BATCH)   // 272 blocks
#define NT 256

// ---------------- device scratch (no allocations allowed) ----------------
__device__ double   g_acc[BATCH][5];      // bond_num, bond_den, ce, csum, msum (zero; tail resets)
__device__ double   g_mom[BATCH][17];     // W, Mask, Swx[3], Swg[3], Sxg[9]
__device__ float    g_watom[BATCH][NATOM];
__device__ unsigned g_done = 0;           // tail resets to 0 each launch

__device__ __forceinline__ float sqrt_approx(float v) {
    float y; asm("sqrt.approx.f32 %0, %1;" : "=f"(y) : "f"(v)); return y;
}

__device__ __forceinline__ float det3f(float a00, float a01, float a02,
                                       float a10, float a11, float a12,
                                       float a20, float a21, float a22) {
    return a00*(a11*a22 - a12*a21) - a01*(a10*a22 - a12*a20) + a02*(a10*a21 - a11*a20);
}

__global__ void __launch_bounds__(NT, 2)
fused_kernel(const float* __restrict__ x, const float* __restrict__ gt,
             const float* __restrict__ gmask,
             const float* __restrict__ isp, const float* __restrict__ isd,
             const float* __restrict__ isr, const float* __restrict__ isl,
             const float* __restrict__ tmask, const int* __restrict__ npt,
             const float* __restrict__ tb, const float* __restrict__ t,
             float* __restrict__ out) {
    int blk = blockIdx.x;
    int tid = threadIdx.x;
    int b = blk & 1;
    int p = blk >> 1;
    int I = 0, rem = p;
    while (rem >= (NTILE - I)) { rem -= (NTILE - I); I++; }
    int J = I + rem;

    __shared__ int    cum[NTOK];
    __shared__ float4 sx0[128], sg0[128], sx1[128], sg1[128];
    __shared__ int    str0[128], str1[128];      // absolute token per atom
    __shared__ float  saL0[128], sp0[128], saL1[128], sp1[128];
    __shared__ float  Stile[32 * 32];
    __shared__ int    s_tIlo, s_tJlo, s_fast;

    // ---- local token scan --------------------------------------------------
    cum[tid] = npt[b * NTOK + tid];
    __syncthreads();
    for (int off = 1; off < NTOK; off <<= 1) {
        int v = (tid >= off) ? cum[tid - off] : 0;
        __syncthreads();
        cum[tid] += v;
        __syncthreads();
    }
    int total = cum[NTOK - 1];

    // ---- local atom prep for my two tiles ----------------------------------
    {
        int tile  = (tid < 128) ? I : J;
        int local = tid & 127;
        int l = tile * 128 + local;
        int ls = l < total ? l : (total > 0 ? total - 1 : 0);
        int lo = 0, hi = NTOK - 1;
        while (lo < hi) {
            int mid = (lo + hi) >> 1;
            if (cum[mid] > ls) hi = mid; else lo = mid + 1;
        }
        int tok = lo;
        float valid = (l < total) ? 1.f : 0.f;
        float tm = tmask[b * NTOK + tok] * valid;
        float dv = isd[b * NTOK + tok], rv = isr[b * NTOK + tok];
        float lv = isl[b * NTOK + tok], pv = isp[b * NTOK + tok];
        float nuc = (dv + rv) * tm;
        float aL  = lv * tm;
        float pL  = (pv + dv + rv) * tm;
        float mk  = gmask[(size_t)b * NATOM + l];
        float4 vx = make_float4(x[(size_t)b*NATOM*3 + 3*l], x[(size_t)b*NATOM*3 + 3*l+1],
                                x[(size_t)b*NATOM*3 + 3*l+2], mk);
        float4 vg = make_float4(gt[(size_t)b*NATOM*3 + 3*l], gt[(size_t)b*NATOM*3 + 3*l+1],
                                gt[(size_t)b*NATOM*3 + 3*l+2], nuc);
        if (tid < 128) {
            sx0[local] = vx; sg0[local] = vg; str0[local] = tok;
            saL0[local] = aL; sp0[local] = pL;
            if (local == 0) s_tIlo = tok;
        } else {
            sx1[local] = vx; sg1[local] = vg; str1[local] = tok;
            saL1[local] = aL; sp1[local] = pL;
            if (local == 0) s_tJlo = tok;
        }
    }
    __syncthreads();
    if (tid == 0)
        s_fast = ((str0[127] - s_tIlo) < 32 && (str1[127] - s_tJlo) < 32) ? 1 : 0;
    __syncthreads();

    const float* tbb = tb + (size_t)b * NTOK * NTOK;
    int tIlo = s_tIlo, tJlo = s_tJlo;
    int fast = s_fast;

    // ---- local 32x32 token S-tile ------------------------------------------
    if (fast) {
        for (int e = tid; e < 1024; e += NT) {
            int a = e >> 5, c = e & 31;
            int ti = tIlo + a, tj = tJlo + c;
            float v = 0.f;
            if (ti < NTOK && tj < NTOK) {
                float tmi = tmask[b*NTOK+ti], tmj = tmask[b*NTOK+tj];
                float ai = isl[b*NTOK+ti] * tmi;
                float aj = isl[b*NTOK+tj] * tmj;
                float pi = (isp[b*NTOK+ti] + isd[b*NTOK+ti] + isr[b*NTOK+ti]) * tmi;
                float pj = (isp[b*NTOK+tj] + isd[b*NTOK+tj] + isr[b*NTOK+tj]) * tmj;
                v = tbb[ti * NTOK + tj] * ai * pj + tbb[tj * NTOK + ti] * aj * pi;
            }
            Stile[e] = v;
        }
        __syncthreads();
    }

    // ---- pairwise loop over this tile pair ---------------------------------
    {
        int r  = tid >> 1;
        int jb = (tid & 1) << 6;
        float4 rx = sx0[r], rg = sg0[r];
        int   ti_abs = str0[r];
        int   rel_i  = min(ti_abs - tIlo, 31);
        const float* Srow = &Stile[rel_i << 5];
        float aLi = saL0[r], pLi = sp0[r];
        bool diag = (I == J);

        const float n1 = 0.846045767f,  n2 = 0.187663961f,  n3 = 0.0091748690f;
        const float d1 = 1.128061023f,  d2 = 0.375327923f,  d3 = 0.036699476f, d4 = 0.00055308437f;

        float a0 = 0.f, a1 = 0.f, a2 = 0.f, a3 = 0.f, a4 = 0.f;

        #pragma unroll 4
        for (int jj = 0; jj < 64; jj++) {
            int j = jb + jj;
            float4 cx = sx1[j], cg = sg1[j];

            float valid = (!diag || (j > r)) ? 1.f : 0.f;
            float pm = rx.w * cx.w * valid;

            float dd0 = rx.x - cx.x, dd1 = rx.y - cx.y, dd2 = rx.z - cx.z;
            float dxv = sqrt_approx(fmaf(dd0, dd0, fmaf(dd1, dd1, fmaf(dd2, dd2, 1e-12f))));

            float ee0 = rg.x - cg.x, ee1 = rg.y - cg.y, ee2 = rg.z - cg.z;
            float dgv = sqrt_approx(fmaf(ee0, ee0, fmaf(ee1, ee1, fmaf(ee2, ee2, 1e-12f))));

            float diff = dxv - dgv;
            float wS;
            if (fast) {
                int rel_j = min(str1[j] - tJlo, 31);
                wS = Srow[rel_j];
            } else {
                int tj_abs = str1[j];
                wS = __ldg(&tbb[ti_abs * NTOK + tj_abs]) * aLi * sp1[j]
                   + __ldg(&tbb[tj_abs * NTOK + ti_abs]) * saL1[j] * pLi;
            }
            float wbs = wS * pm;
            a0 = fmaf(diff * diff, wbs, a0);
            a1 += wbs;

            float d = fminf(fabsf(diff), 20.f);
            float E = __expf(d);
            float num = fmaf(fmaf(fmaf(n3, E, n2), E, n1), E, 1.f);
            float den = fmaf(fmaf(fmaf(fmaf(d4, E, d3), E, d2), E, d1), E, 1.f);
            float e   = __fdividef(num, den);

            float lt15 = (dgv < 15.f) ? 1.f : 0.f;
            float lt30 = (dgv < 30.f) ? 1.f : 0.f;
            float csum = fmaf(rg.w + cg.w, lt30 - lt15, 2.f * lt15) * pm;

            a2 = fmaf(csum, e, a2);
            a3 += csum;
            a4 += 2.f * pm;
        }

        __shared__ float red2[8][5];
        int lane = tid & 31, w = tid >> 5;
        float vals[5] = {a0, a1, a2, a3, a4};
        #pragma unroll
        for (int k = 0; k < 5; k++) {
            float v = vals[k];
            for (int off = 16; off > 0; off >>= 1) v += __shfl_xor_sync(0xffffffffu, v, off);
            if (lane == 0) red2[w][k] = v;
        }
        __syncthreads();
        if (tid < 5) {
            float ssum = 0.f;
            #pragma unroll
            for (int ww = 0; ww < 8; ww++) ssum += red2[ww][tid];
            atomicAdd(&g_acc[b][tid], (double)ssum);
        }
    }

    // ---- blocks 0/1: FP64 moments + watom + bond diagonal ------------------
    if (blk < BATCH) {
        const float* xb = x  + (size_t)b * NATOM * 3;
        const float* gb = gt + (size_t)b * NATOM * 3;
        const float* mb = gmask + (size_t)b * NATOM;

        double s[18];
        #pragma unroll
        for (int q = 0; q < 18; q++) s[q] = 0.0;

        for (int k = 0; k < NATOM / NT; k++) {
            int l = k * NT + tid;
            int ls = l < total ? l : (total > 0 ? total - 1 : 0);
            int lo = 0, hi = NTOK - 1;
            while (lo < hi) {
                int mid = (lo + hi) >> 1;
                if (cum[mid] > ls) hi = mid; else lo = mid + 1;
            }
            int tok = lo;
            float valid = (l < total) ? 1.f : 0.f;
            float tm = tmask[b * NTOK + tok] * valid;
            float dv = isd[b * NTOK + tok], rv = isr[b * NTOK + tok];
            float lv = isl[b * NTOK + tok], pv = isp[b * NTOK + tok];
            float w_at = (1.0f + 5.0f * dv + 5.0f * rv + 10.0f * lv) * tm;
            float aL = lv * tm, bL = (pv + dv + rv) * tm;

            float mk = mb[l];
            float x0 = xb[3*l+0], x1 = xb[3*l+1], x2 = xb[3*l+2];
            float g0 = gb[3*l+0], g1 = gb[3*l+1], g2 = gb[3*l+2];

            g_watom[b][l] = w_at;

            double wm = (double)(w_at * mk);
            s[0] += wm; s[1] += (double)mk;
            s[2] += wm*x0; s[3] += wm*x1; s[4] += wm*x2;
            s[5] += wm*g0; s[6] += wm*g1; s[7] += wm*g2;
            s[8]  += wm*x0*g0; s[9]  += wm*x0*g1; s[10] += wm*x0*g2;
            s[11] += wm*x1*g0; s[12] += wm*x1*g1; s[13] += wm*x1*g2;
            s[14] += wm*x2*g0; s[15] += wm*x2*g1; s[16] += wm*x2*g2;
            s[17] += (double)(aL * bL * __ldg(&tbb[tok * NTOK + tok]) * mk * mk);
        }

        __shared__ double redm[8][18];
        int lane = tid & 31, w = tid >> 5;
        #pragma unroll
        for (int q = 0; q < 18; q++) {
            double v = s[q];
            for (int off = 16; off > 0; off >>= 1) v += __shfl_xor_sync(0xffffffffu, v, off);
            if (lane == 0) redm[w][q] = v;
        }
        __syncthreads();
        if (tid < 17) {
            double v = 0.0;
            #pragma unroll
            for (int ww = 0; ww < 8; ww++) v += redm[ww][tid];
            g_mom[b][tid] = v;
        }
        if (tid == 17) {
            double v = 0.0;
            #pragma unroll
            for (int ww = 0; ww < 8; ww++) v += redm[ww][17];
            atomicAdd(&g_acc[b][1], v);   // bond-denominator diagonal
        }
    }

    // ---- done-counter: last finishing block runs the tail -------------------
    __shared__ int s_last;
    __threadfence();
    __syncthreads();
    if (tid == 0) {
        unsigned v = atomicAdd(&g_done, 1u);
        s_last = (v == GRID - 1) ? 1 : 0;
    }
    __syncthreads();
    if (!s_last) return;
    __threadfence();   // acquire side

    // =========== tail: QCP Kabsch + weighted MSE + final =====================
    __shared__ float sR[BATCH][15];
    __shared__ double sred[8];

    if (tid < BATCH) {
        int bb = tid;
        double W = g_mom[bb][0];
        double invW = 1.0 / W;
        double sx[3] = {g_mom[bb][2], g_mom[bb][3], g_mom[bb][4]};
        double sg[3] = {g_mom[bb][5], g_mom[bb][6], g_mom[bb][7]};
        double H[3][3];
        for (int i = 0; i < 3; i++)
            for (int j = 0; j < 3; j++)
                H[i][j] = g_mom[bb][8 + i * 3 + j] - sx[i] * sg[j] * invW;

        double Sxx = H[0][0], Sxy = H[1][0], Sxz = H[2][0];
        double Syx = H[0][1], Syy = H[1][1], Syz = H[2][1];
        double Szx = H[0][2], Szy = H[1][2], Szz = H[2][2];

        double Nd[4][4] = {
            { Sxx+Syy+Szz,  Syz-Szy,       Szx-Sxz,       Sxy-Syx      },
            { Syz-Szy,      Sxx-Syy-Szz,   Sxy+Syx,       Szx+Sxz      },
            { Szx-Sxz,      Sxy+Syx,      -Sxx+Syy-Szz,   Syz+Szy      },
            { Sxy-Syx,      Szx+Sxz,       Syz+Szy,      -Sxx-Syy+Szz  }};

        double fro = 0.0;
        for (int i = 0; i < 4; i++) for (int j = 0; j < 4; j++) fro += Nd[i][j]*Nd[i][j];
        double scl = 1.0 / sqrt(fro + 1e-300);

        float N[4][4];
        for (int i = 0; i < 4; i++)
            for (int j = 0; j < 4; j++) N[i][j] = (float)(Nd[i][j] * scl);

        float N2[4][4]; float t3 = 0.f, t4 = 0.f;
        #pragma unroll
        for (int i = 0; i < 4; i++)
            #pragma unroll
            for (int j = 0; j < 4; j++) {
                float v = 0.f;
                #pragma unroll
                for (int k = 0; k < 4; k++) v = fmaf(N[i][k], N[k][j], v);
                N2[i][j] = v;
            }
        #pragma unroll
        for (int i = 0; i < 4; i++)
            #pragma unroll
            for (int j = 0; j < 4; j++) {
                t3 = fmaf(N2[i][j], N[i][j], t3);
                t4 = fmaf(N2[i][j], N2[i][j], t4);
            }
        const float a2c = -0.5f;
        float a1c = -t3 * (1.f / 3.f);
        float a0c = 0.125f - 0.25f * t4;

        float lam = 1.0f;
        #pragma unroll
        for (int it = 0; it < 16; it++) {
            float pp = fmaf(fmaf(fmaf(lam, lam, a2c), lam, a1c), lam, a0c);
            float dp = fmaf(fmaf(4.f, lam * lam, 2.f * a2c), lam, a1c);
            lam -= __fdividef(pp, dp);
        }

        float M[4][4];
        for (int i = 0; i < 4; i++)
            for (int j = 0; j < 4; j++) M[i][j] = N[i][j] - ((i == j) ? lam : 0.f);

        float adj[4][4];
        const int rows[4][3] = {{1,2,3},{0,2,3},{0,1,3},{0,1,2}};
        #pragma unroll
        for (int i = 0; i < 4; i++)
            #pragma unroll
            for (int j = 0; j < 4; j++) {
                const int* rr = rows[j];
                const int* cc = rows[i];
                float m3 = det3f(M[rr[0]][cc[0]], M[rr[0]][cc[1]], M[rr[0]][cc[2]],
                                 M[rr[1]][cc[0]], M[rr[1]][cc[1]], M[rr[1]][cc[2]],
                                 M[rr[2]][cc[0]], M[rr[2]][cc[1]], M[rr[2]][cc[2]]);
                adj[i][j] = (((i + j) & 1) ? -m3 : m3);
            }
        int bestc = 0; float bestn = -1.f;
        #pragma unroll
        for (int j = 0; j < 4; j++) {
            float nn = 0.f;
            #pragma unroll
            for (int i = 0; i < 4; i++) nn = fmaf(adj[i][j], adj[i][j], nn);
            if (nn > bestn) { bestn = nn; bestc = j; }
        }
        float qn = __fdividef(1.f, sqrtf(bestn));
        float q0 = adj[0][bestc] * qn, q1 = adj[1][bestc] * qn;
        float q2 = adj[2][bestc] * qn, q3 = adj[3][bestc] * qn;

        float R[3][3] = {
            {1.f-2.f*(q2*q2+q3*q3), 2.f*(q1*q2-q0*q3),     2.f*(q1*q3+q0*q2)},
            {2.f*(q1*q2+q0*q3),     1.f-2.f*(q1*q1+q3*q3), 2.f*(q2*q3-q0*q1)},
            {2.f*(q1*q3-q0*q2),     2.f*(q2*q3+q0*q1),     1.f-2.f*(q1*q1+q2*q2)}};

        float f1 = 0.f, f2 = 0.f;
        for (int i = 0; i < 3; i++)
            for (int j = 0; j < 3; j++) {
                float Hf = (float)(H[i][j] * scl);
                f1 = fmaf(R[i][j], Hf, f1);
                f2 = fmaf(R[j][i], Hf, f2);
            }
        if (f2 > f1) {
            for (int i = 0; i < 3; i++)
                for (int j = i + 1; j < 3; j++) { float tmp = R[i][j]; R[i][j] = R[j][i]; R[j][i] = tmp; }
        }

        for (int i = 0; i < 3; i++)
            for (int j = 0; j < 3; j++) sR[bb][i*3+j] = R[i][j];
        for (int i = 0; i < 3; i++) {
            sR[bb][9+i]  = (float)(sg[i] * invW);
            sR[bb][12+i] = (float)(sx[i] * invW);
        }
    }
    __syncthreads();

    {
        int bb = tid >> 7;
        int at = tid & 127;

        float R00 = sR[bb][0], R01 = sR[bb][1], R02 = sR[bb][2];
        float R10 = sR[bb][3], R11 = sR[bb][4], R12 = sR[bb][5];
        float R20 = sR[bb][6], R21 = sR[bb][7], R22 = sR[bb][8];
        float mg0 = sR[bb][9],  mg1 = sR[bb][10], mg2 = sR[bb][11];
        float mx0 = sR[bb][12], mx1 = sR[bb][13], mx2 = sR[bb][14];

        const float* xb = x  + (size_t)bb * NATOM * 3;
        const float* gb = gt + (size_t)bb * NATOM * 3;
        const float* mb = gmask + (size_t)bb * NATOM;

        double s = 0.0;
        for (int k = 0; k < NATOM / 128; k++) {
            int l = k * 128 + at;
            float g0 = gb[3*l+0] - mg0, g1 = gb[3*l+1] - mg1, g2 = gb[3*l+2] - mg2;
            float c0 = R00*g0 + R01*g1 + R02*g2 + mx0;
            float c1 = R10*g0 + R11*g1 + R12*g2 + mx1;
            float c2 = R20*g0 + R21*g1 + R22*g2 + mx2;
            float e0 = xb[3*l+0] - c0, e1 = xb[3*l+1] - c1, e2 = xb[3*l+2] - c2;
            float e = e0*e0 + e1*e1 + e2*e2;
            s += (double)(e * g_watom[bb][l] * mb[l]);
        }

        int lane = tid & 31, w = tid >> 5;   // warps 0-3 = b0, 4-7 = b1
        for (int off = 16; off > 0; off >>= 1) s += __shfl_xor_sync(0xffffffffu, s, off);
        if (lane == 0) sred[w] = s;
        __syncthreads();

        if (tid == 0) {
            double loss = 0.0;
            for (int bb2 = 0; bb2 < BATCH; bb2++) {
                double mse = 0.0;
                for (int ww = 0; ww < 4; ww++) mse += sred[bb2 * 4 + ww];
                double lbond = g_acc[bb2][0] / g_acc[bb2][1];
                double ce_m  = g_acc[bb2][2] / g_acc[bb2][4];
                double c_m   = g_acc[bb2][3] / g_acc[bb2][4];
                double llddt = 1.0 - ce_m / c_m;
                double lmse  = (mse / g_mom[bb2][1]) * (1.0 / 3.0);
                double tv = (double)t[bb2];
                double wt = (tv * tv + 256.0) / ((tv + 16.0) * (tv + 16.0));
                loss += wt * (lmse + lbond) + llddt;
            }
            out[0] = (float)(loss / BATCH);

            // reset accumulators for graph replay
            for (int bb2 = 0; bb2 < BATCH; bb2++)
                for (int q = 0; q < 5; q++) g_acc[bb2][q] = 0.0;
            __threadfence();
            atomicExch(&g_done, 0u);
        }
    }
}

// ---------------- launch ---------------------------------------------------
extern "C" void kernel_launch(void* const* d_in, const int* in_sizes, int n_in,
                              void* d_out, int out_size) {
    const float* x   = (const float*)d_in[0];
    const float* gt  = (const float*)d_in[1];
    const float* gm  = (const float*)d_in[2];
    const float* isp = (const float*)d_in[3];
    const float* isd = (const float*)d_in[4];
    const float* isr = (const float*)d_in[5];
    const float* isl = (const float*)d_in[6];
    const float* tb  = (const float*)d_in[7];
    const float* tm  = (const float*)d_in[8];
    const int*   npt = (const int*)d_in[9];
    const float* t   = (const float*)d_in[10];
    float* out = (float*)d_out;

    fused_kernel<<<GRID, NT>>>(x, gt, gm, isp, isd, isr, isl, tm, npt, tb, t, out);
}

// round 7
// speedup vs baseline: 1.2283x; 1.1770x over previous
#include <cuda_runtime.h>
#include <math.h>

#define BATCH 2
#define NTOK 256
#define NATOM 2048
#define TSZ 64                   // atoms per tile
#define NTILE 32                 // NATOM / TSZ
#define TPAIRS 528               // NTILE*(NTILE+1)/2
#define GRID (TPAIRS * BATCH)    // 1056 blocks
#define NT 128
#define NBUK 16

// ---------------- device scratch (no allocations allowed) ----------------
__device__ double   g_acc[BATCH][4][NBUK];  // bond_num, bond_den, ce, c (tail resets)
__device__ double   g_mom[BATCH][17];       // W, Mask, Swx[3], Swg[3], Sxg[9]
__device__ float    g_watom[BATCH][NATOM];
__device__ unsigned g_done = 0;             // tail resets

__device__ __forceinline__ float sqrt_approx(float v) {
    float y; asm("sqrt.approx.f32 %0, %1;" : "=f"(y) : "f"(v)); return y;
}

__device__ __forceinline__ float det3f(float a00, float a01, float a02,
                                       float a10, float a11, float a12,
                                       float a20, float a21, float a22) {
    return a00*(a11*a22 - a12*a21) - a01*(a10*a22 - a12*a20) + a02*(a10*a21 - a11*a20);
}

// ---------------- hot inner loop (branches hoisted via template) ----------
template<bool FAST, bool DIAG>
__device__ __forceinline__ void pair_loop(
    int tid,
    const float4* sx0, const float4* sg0, const float4* sx1, const float4* sg1,
    const int* srel0, const int* srel1, const int* sab0, const int* sab1,
    const float* saL0, const float* sp0, const float* saL1, const float* sp1,
    const float* Stile, const float* tbb,
    float& a0, float& a1, float& a2, float& a3)
{
    int r  = tid >> 1;
    int jb = (tid & 1) << 5;
    float4 rx = sx0[r], rg = sg0[r];
    const float* Srow = FAST ? &Stile[srel0[r] << 5] : Stile;
    int   ti_abs = FAST ? 0   : sab0[r];
    float aLi    = FAST ? 0.f : saL0[r];
    float pLi    = FAST ? 0.f : sp0[r];

    const float n1 = 0.846045767f,  n2 = 0.187663961f,  n3 = 0.0091748690f;
    const float q1 = 1.128061023f,  q2 = 0.375327923f,  q3 = 0.036699476f, q4 = 0.00055308437f;

    #pragma unroll 4
    for (int jj = 0; jj < 32; jj++) {
        int j = jb + jj;
        float4 cx = sx1[j], cg = sg1[j];
        float pm = rx.w * cx.w;
        if (DIAG) pm = (j > r) ? pm : 0.f;

        float dd0 = rx.x - cx.x, dd1 = rx.y - cx.y, dd2 = rx.z - cx.z;
        float dxv = sqrt_approx(fmaf(dd0, dd0, fmaf(dd1, dd1, fmaf(dd2, dd2, 1e-12f))));

        float ee0 = rg.x - cg.x, ee1 = rg.y - cg.y, ee2 = rg.z - cg.z;
        float dgv = sqrt_approx(fmaf(ee0, ee0, fmaf(ee1, ee1, fmaf(ee2, ee2, 1e-12f))));

        float diff = dxv - dgv;
        float wS;
        if (FAST) {
            wS = Srow[srel1[j]];
        } else {
            int tj = sab1[j];
            wS = __ldg(&tbb[ti_abs * NTOK + tj]) * aLi * sp1[j]
               + __ldg(&tbb[tj * NTOK + ti_abs]) * saL1[j] * pLi;
        }
        float wbs = wS * pm;
        a0 = fmaf(diff * diff, wbs, a0);
        a1 += wbs;

        float d = fminf(fabsf(diff), 20.f);
        float E = __expf(d);
        float num = fmaf(fmaf(fmaf(n3, E, n2), E, n1), E, 1.f);
        float den = fmaf(fmaf(fmaf(fmaf(q4, E, q3), E, q2), E, q1), E, 1.f);
        float e   = __fdividef(num, den);

        float lt15 = (dgv < 15.f) ? 1.f : 0.f;
        float lt30 = (dgv < 30.f) ? 1.f : 0.f;
        float csum = fmaf(rg.w + cg.w, lt30 - lt15, 2.f * lt15) * pm;

        a2 = fmaf(csum, e, a2);
        a3 += csum;
    }
}

__global__ void __launch_bounds__(NT, 8)
fused_kernel(const float* __restrict__ x, const float* __restrict__ gt,
             const float* __restrict__ gmask,
             const float* __restrict__ isp, const float* __restrict__ isd,
             const float* __restrict__ isr, const float* __restrict__ isl,
             const float* __restrict__ tmask, const int* __restrict__ npt,
             const float* __restrict__ tb, const float* __restrict__ t,
             float* __restrict__ out) {
    int blk = blockIdx.x;
    int tid = threadIdx.x;
    int b = blk & 1;
    int p = blk >> 1;
    int I = 0, rem = p;
    while (rem >= (NTILE - I)) { rem -= (NTILE - I); I++; }
    int J = I + rem;

    __shared__ int    cum[NTOK];
    __shared__ float4 sx0[TSZ], sg0[TSZ], sx1[TSZ], sg1[TSZ];
    __shared__ int    sab0[TSZ], sab1[TSZ], srel0[TSZ], srel1[TSZ];
    __shared__ float  saL0[TSZ], sp0[TSZ], saL1[TSZ], sp1[TSZ];
    __shared__ float  Stile[1024];
    __shared__ int    s_fast, s_tIlo, s_tJlo;
    __shared__ int    s_wsum[4];

    const float* tbb = tb + (size_t)b * NTOK * NTOK;
    int lane = tid & 31, warp = tid >> 5;

    // ---- token prefix scan: 128 threads, 2 elements each --------------------
    {
        int v0 = npt[b * NTOK + 2 * tid];
        int v1 = npt[b * NTOK + 2 * tid + 1];
        int s = v0 + v1;
        #pragma unroll
        for (int off = 1; off < 32; off <<= 1) {
            int n = __shfl_up_sync(0xffffffffu, s, off);
            if (lane >= off) s += n;
        }
        if (lane == 31) s_wsum[warp] = s;
        __syncthreads();
        int base = 0;
        for (int w = 0; w < 4; w++) if (w < warp) base += s_wsum[w];
        int incl1 = base + s;
        cum[2 * tid]     = incl1 - v1;
        cum[2 * tid + 1] = incl1;
        __syncthreads();
    }
    int total = cum[NTOK - 1];

    // ---- atom prep: one atom per thread --------------------------------------
    {
        int tile  = (tid < TSZ) ? I : J;
        int local = tid & (TSZ - 1);
        int l = tile * TSZ + local;
        int ls = l < total ? l : (total > 0 ? total - 1 : 0);
        int lo = 0, hi = NTOK - 1;
        while (lo < hi) {
            int mid = (lo + hi) >> 1;
            if (cum[mid] > ls) hi = mid; else lo = mid + 1;
        }
        int tok = lo;
        float valid = (l < total) ? 1.f : 0.f;
        float tm = tmask[b * NTOK + tok] * valid;
        float dv = isd[b * NTOK + tok], rv = isr[b * NTOK + tok];
        float lv = isl[b * NTOK + tok], pv = isp[b * NTOK + tok];
        float nuc = (dv + rv) * tm;
        float aL  = lv * tm;
        float pL  = (pv + dv + rv) * tm;
        float mk  = gmask[(size_t)b * NATOM + l];
        float4 vx = make_float4(x[(size_t)b*NATOM*3 + 3*l], x[(size_t)b*NATOM*3 + 3*l+1],
                                x[(size_t)b*NATOM*3 + 3*l+2], mk);
        float4 vg = make_float4(gt[(size_t)b*NATOM*3 + 3*l], gt[(size_t)b*NATOM*3 + 3*l+1],
                                gt[(size_t)b*NATOM*3 + 3*l+2], nuc);
        if (tid < TSZ) {
            sx0[local] = vx; sg0[local] = vg; sab0[local] = tok;
            saL0[local] = aL; sp0[local] = pL;
        } else {
            sx1[local] = vx; sg1[local] = vg; sab1[local] = tok;
            saL1[local] = aL; sp1[local] = pL;
        }
    }
    __syncthreads();
    if (tid == 0) {
        s_tIlo = sab0[0]; s_tJlo = sab1[0];
        s_fast = ((sab0[TSZ-1] - sab0[0]) < 32 && (sab1[TSZ-1] - sab1[0]) < 32) ? 1 : 0;
    }
    __syncthreads();
    int fast = s_fast;  // uniform across block

    if (fast) {
        int tIlo = s_tIlo, tJlo = s_tJlo;
        if (tid < TSZ) srel0[tid] = min(sab0[tid] - tIlo, 31);
        else           srel1[tid - TSZ] = min(sab1[tid - TSZ] - tJlo, 31);
        for (int e = tid; e < 1024; e += NT) {
            int a = e >> 5, c = e & 31;
            int ti = tIlo + a, tj = tJlo + c;
            float v = 0.f;
            if (ti < NTOK && tj < NTOK) {
                float tmi = tmask[b*NTOK+ti], tmj = tmask[b*NTOK+tj];
                float ai = isl[b*NTOK+ti] * tmi;
                float aj = isl[b*NTOK+tj] * tmj;
                float pi = (isp[b*NTOK+ti] + isd[b*NTOK+ti] + isr[b*NTOK+ti]) * tmi;
                float pj = (isp[b*NTOK+tj] + isd[b*NTOK+tj] + isr[b*NTOK+tj]) * tmj;
                v = tbb[ti * NTOK + tj] * ai * pj + tbb[tj * NTOK + ti] * aj * pi;
            }
            Stile[e] = v;
        }
        __syncthreads();
    }

    // ---- pairwise loop --------------------------------------------------------
    float a0 = 0.f, a1 = 0.f, a2 = 0.f, a3 = 0.f;
    if (fast) {
        if (I == J) pair_loop<true, true >(tid, sx0, sg0, sx1, sg1, srel0, srel1, sab0, sab1,
                                           saL0, sp0, saL1, sp1, Stile, tbb, a0, a1, a2, a3);
        else        pair_loop<true, false>(tid, sx0, sg0, sx1, sg1, srel0, srel1, sab0, sab1,
                                           saL0, sp0, saL1, sp1, Stile, tbb, a0, a1, a2, a3);
    } else {
        if (I == J) pair_loop<false, true >(tid, sx0, sg0, sx1, sg1, srel0, srel1, sab0, sab1,
                                            saL0, sp0, saL1, sp1, Stile, tbb, a0, a1, a2, a3);
        else        pair_loop<false, false>(tid, sx0, sg0, sx1, sg1, srel0, srel1, sab0, sab1,
                                            saL0, sp0, saL1, sp1, Stile, tbb, a0, a1, a2, a3);
    }

    // ---- block reduce + bucketed atomics --------------------------------------
    {
        __shared__ float red2[4][4];
        float vals[4] = {a0, a1, a2, a3};
        #pragma unroll
        for (int k = 0; k < 4; k++) {
            float v = vals[k];
            for (int off = 16; off > 0; off >>= 1) v += __shfl_xor_sync(0xffffffffu, v, off);
            if (lane == 0) red2[warp][k] = v;
        }
        __syncthreads();
        if (tid < 4) {
            float ssum = red2[0][tid] + red2[1][tid] + red2[2][tid] + red2[3][tid];
            atomicAdd(&g_acc[b][tid][(blk >> 1) & (NBUK - 1)], (double)ssum);
        }
    }

    // ---- blocks 0/1: moments (fp32 partials) + watom + bond diagonal ----------
    if (blk < BATCH) {
        const float* xb = x  + (size_t)b * NATOM * 3;
        const float* gb = gt + (size_t)b * NATOM * 3;
        const float* mb = gmask + (size_t)b * NATOM;

        float s[18];
        #pragma unroll
        for (int q = 0; q < 18; q++) s[q] = 0.f;

        for (int k = 0; k < NATOM / NT; k++) {
            int l = k * NT + tid;
            int ls = l < total ? l : (total > 0 ? total - 1 : 0);
            int lo = 0, hi = NTOK - 1;
            while (lo < hi) {
                int mid = (lo + hi) >> 1;
                if (cum[mid] > ls) hi = mid; else lo = mid + 1;
            }
            int tok = lo;
            float valid = (l < total) ? 1.f : 0.f;
            float tm = tmask[b * NTOK + tok] * valid;
            float dv = isd[b * NTOK + tok], rv = isr[b * NTOK + tok];
            float lv = isl[b * NTOK + tok], pv = isp[b * NTOK + tok];
            float w_at = (1.0f + 5.0f * dv + 5.0f * rv + 10.0f * lv) * tm;
            float aL = lv * tm, bL = (pv + dv + rv) * tm;

            float mk = mb[l];
            float x0 = xb[3*l+0], x1 = xb[3*l+1], x2 = xb[3*l+2];
            float g0 = gb[3*l+0], g1 = gb[3*l+1], g2 = gb[3*l+2];

            g_watom[b][l] = w_at;

            float wm = w_at * mk;
            s[0] += wm; s[1] += mk;
            s[2] = fmaf(wm, x0, s[2]); s[3] = fmaf(wm, x1, s[3]); s[4] = fmaf(wm, x2, s[4]);
            s[5] = fmaf(wm, g0, s[5]); s[6] = fmaf(wm, g1, s[6]); s[7] = fmaf(wm, g2, s[7]);
            s[8]  = fmaf(wm*x0, g0, s[8]);  s[9]  = fmaf(wm*x0, g1, s[9]);  s[10] = fmaf(wm*x0, g2, s[10]);
            s[11] = fmaf(wm*x1, g0, s[11]); s[12] = fmaf(wm*x1, g1, s[12]); s[13] = fmaf(wm*x1, g2, s[13]);
            s[14] = fmaf(wm*x2, g0, s[14]); s[15] = fmaf(wm*x2, g1, s[15]); s[16] = fmaf(wm*x2, g2, s[16]);
            s[17] = fmaf(aL * bL * __ldg(&tbb[tok * NTOK + tok]), mk * mk, s[17]);
        }

        __shared__ double redm[4][18];
        #pragma unroll
        for (int q = 0; q < 18; q++) {
            double v = (double)s[q];
            for (int off = 16; off > 0; off >>= 1) v += __shfl_xor_sync(0xffffffffu, v, off);
            if (lane == 0) redm[warp][q] = v;
        }
        __syncthreads();
        if (tid < 17) {
            g_mom[b][tid] = redm[0][tid] + redm[1][tid] + redm[2][tid] + redm[3][tid];
        }
        if (tid == 17) {
            double v = redm[0][17] + redm[1][17] + redm[2][17] + redm[3][17];
            atomicAdd(&g_acc[b][1][0], v);   // bond-denominator diagonal
        }
    }

    // ---- done counter: last finishing block runs the tail ----------------------
    __shared__ int s_last;
    __threadfence();
    __syncthreads();
    if (tid == 0) {
        unsigned v = atomicAdd(&g_done, 1u);
        s_last = (v == GRID - 1) ? 1 : 0;
    }
    __syncthreads();
    if (!s_last) return;
    __threadfence();   // acquire

    // =========== tail: QCP Kabsch + weighted MSE + final ========================
    __shared__ float sR[BATCH][15];
    __shared__ double sred[4];

    if (tid < BATCH) {
        int bb = tid;
        double W = g_mom[bb][0];
        double invW = 1.0 / W;
        double sx[3] = {g_mom[bb][2], g_mom[bb][3], g_mom[bb][4]};
        double sg[3] = {g_mom[bb][5], g_mom[bb][6], g_mom[bb][7]};
        double H[3][3];
        for (int i = 0; i < 3; i++)
            for (int j = 0; j < 3; j++)
                H[i][j] = g_mom[bb][8 + i * 3 + j] - sx[i] * sg[j] * invW;

        double Sxx = H[0][0], Sxy = H[1][0], Sxz = H[2][0];
        double Syx = H[0][1], Syy = H[1][1], Syz = H[2][1];
        double Szx = H[0][2], Szy = H[1][2], Szz = H[2][2];

        double Nd[4][4] = {
            { Sxx+Syy+Szz,  Syz-Szy,       Szx-Sxz,       Sxy-Syx      },
            { Syz-Szy,      Sxx-Syy-Szz,   Sxy+Syx,       Szx+Sxz      },
            { Szx-Sxz,      Sxy+Syx,      -Sxx+Syy-Szz,   Syz+Szy      },
            { Sxy-Syx,      Szx+Sxz,       Syz+Szy,      -Sxx-Syy+Szz  }};

        double fro = 0.0;
        for (int i = 0; i < 4; i++) for (int j = 0; j < 4; j++) fro += Nd[i][j]*Nd[i][j];
        double scl = 1.0 / sqrt(fro + 1e-300);

        float N[4][4];
        for (int i = 0; i < 4; i++)
            for (int j = 0; j < 4; j++) N[i][j] = (float)(Nd[i][j] * scl);

        float N2[4][4]; float t3 = 0.f, t4 = 0.f;
        #pragma unroll
        for (int i = 0; i < 4; i++)
            #pragma unroll
            for (int j = 0; j < 4; j++) {
                float v = 0.f;
                #pragma unroll
                for (int k = 0; k < 4; k++) v = fmaf(N[i][k], N[k][j], v);
                N2[i][j] = v;
            }
        #pragma unroll
        for (int i = 0; i < 4; i++)
            #pragma unroll
            for (int j = 0; j < 4; j++) {
                t3 = fmaf(N2[i][j], N[i][j], t3);
                t4 = fmaf(N2[i][j], N2[i][j], t4);
            }
        const float a2c = -0.5f;
        float a1c = -t3 * (1.f / 3.f);
        float a0c = 0.125f - 0.25f * t4;

        float lam = 1.0f;
        #pragma unroll
        for (int it = 0; it < 16; it++) {
            float pp = fmaf(fmaf(fmaf(lam, lam, a2c), lam, a1c), lam, a0c);
            float dp = fmaf(fmaf(4.f, lam * lam, 2.f * a2c), lam, a1c);
            lam -= __fdividef(pp, dp);
        }

        float M[4][4];
        for (int i = 0; i < 4; i++)
            for (int j = 0; j < 4; j++) M[i][j] = N[i][j] - ((i == j) ? lam : 0.f);

        float adj[4][4];
        const int rows[4][3] = {{1,2,3},{0,2,3},{0,1,3},{0,1,2}};
        #pragma unroll
        for (int i = 0; i < 4; i++)
            #pragma unroll
            for (int j = 0; j < 4; j++) {
                const int* rr = rows[j];
                const int* cc = rows[i];
                float m3 = det3f(M[rr[0]][cc[0]], M[rr[0]][cc[1]], M[rr[0]][cc[2]],
                                 M[rr[1]][cc[0]], M[rr[1]][cc[1]], M[rr[1]][cc[2]],
                                 M[rr[2]][cc[0]], M[rr[2]][cc[1]], M[rr[2]][cc[2]]);
                adj[i][j] = (((i + j) & 1) ? -m3 : m3);
            }
        int bestc = 0; float bestn = -1.f;
        #pragma unroll
        for (int j = 0; j < 4; j++) {
            float nn = 0.f;
            #pragma unroll
            for (int i = 0; i < 4; i++) nn = fmaf(adj[i][j], adj[i][j], nn);
            if (nn > bestn) { bestn = nn; bestc = j; }
        }
        float qn = __fdividef(1.f, sqrtf(bestn));
        float q0 = adj[0][bestc] * qn, q1v = adj[1][bestc] * qn;
        float q2v = adj[2][bestc] * qn, q3v = adj[3][bestc] * qn;

        float R[3][3] = {
            {1.f-2.f*(q2v*q2v+q3v*q3v), 2.f*(q1v*q2v-q0*q3v),      2.f*(q1v*q3v+q0*q2v)},
            {2.f*(q1v*q2v+q0*q3v),      1.f-2.f*(q1v*q1v+q3v*q3v), 2.f*(q2v*q3v-q0*q1v)},
            {2.f*(q1v*q3v-q0*q2v),      2.f*(q2v*q3v+q0*q1v),      1.f-2.f*(q1v*q1v+q2v*q2v)}};

        float f1 = 0.f, f2 = 0.f;
        for (int i = 0; i < 3; i++)
            for (int j = 0; j < 3; j++) {
                float Hf = (float)(H[i][j] * scl);
                f1 = fmaf(R[i][j], Hf, f1);
                f2 = fmaf(R[j][i], Hf, f2);
            }
        if (f2 > f1) {
            for (int i = 0; i < 3; i++)
                for (int j = i + 1; j < 3; j++) { float tmp = R[i][j]; R[i][j] = R[j][i]; R[j][i] = tmp; }
        }

        for (int i = 0; i < 3; i++)
            for (int j = 0; j < 3; j++) sR[bb][i*3+j] = R[i][j];
        for (int i = 0; i < 3; i++) {
            sR[bb][9+i]  = (float)(sg[i] * invW);
            sR[bb][12+i] = (float)(sx[i] * invW);
        }
    }
    __syncthreads();

    {
        int bb = tid >> 6;       // 64 threads per batch
        int at = tid & 63;

        float R00 = sR[bb][0], R01 = sR[bb][1], R02 = sR[bb][2];
        float R10 = sR[bb][3], R11 = sR[bb][4], R12 = sR[bb][5];
        float R20 = sR[bb][6], R21 = sR[bb][7], R22 = sR[bb][8];
        float mg0 = sR[bb][9],  mg1 = sR[bb][10], mg2 = sR[bb][11];
        float mx0 = sR[bb][12], mx1 = sR[bb][13], mx2 = sR[bb][14];

        const float* xb = x  + (size_t)bb * NATOM * 3;
        const float* gb = gt + (size_t)bb * NATOM * 3;
        const float* mb = gmask + (size_t)bb * NATOM;

        double s = 0.0;
        for (int k = 0; k < NATOM / 64; k++) {
            int l = k * 64 + at;
            float g0 = gb[3*l+0] - mg0, g1 = gb[3*l+1] - mg1, g2 = gb[3*l+2] - mg2;
            float c0 = R00*g0 + R01*g1 + R02*g2 + mx0;
            float c1 = R10*g0 + R11*g1 + R12*g2 + mx1;
            float c2 = R20*g0 + R21*g1 + R22*g2 + mx2;
            float e0 = xb[3*l+0] - c0, e1 = xb[3*l+1] - c1, e2 = xb[3*l+2] - c2;
            float e = e0*e0 + e1*e1 + e2*e2;
            s += (double)(e * g_watom[bb][l] * mb[l]);
        }

        for (int off = 16; off > 0; off >>= 1) s += __shfl_xor_sync(0xffffffffu, s, off);
        if (lane == 0) sred[warp] = s;   // warps 0,1 = b0; 2,3 = b1
        __syncthreads();

        if (tid == 0) {
            double loss = 0.0;
            for (int bb2 = 0; bb2 < BATCH; bb2++) {
                double A[4];
                for (int q = 0; q < 4; q++) {
                    double v = 0.0;
                    for (int k = 0; k < NBUK; k++) v += g_acc[bb2][q][k];
                    A[q] = v;
                }
                double mse = sred[bb2 * 2] + sred[bb2 * 2 + 1];
                double lbond = A[0] / A[1];
                double llddt = 1.0 - A[2] / A[3];
                double lmse  = (mse / g_mom[bb2][1]) * (1.0 / 3.0);
                double tv = (double)t[bb2];
                double wt = (tv * tv + 256.0) / ((tv + 16.0) * (tv + 16.0));
                loss += wt * (lmse + lbond) + llddt;
            }
            out[0] = (float)(loss / BATCH);

            // reset accumulators for graph replay
            for (int bb2 = 0; bb2 < BATCH; bb2++)
                for (int q = 0; q < 4; q++)
                    for (int k = 0; k < NBUK; k++) g_acc[bb2][q][k] = 0.0;
            __threadfence();
            atomicExch(&g_done, 0u);
        }
    }
}

// ---------------- launch ---------------------------------------------------
extern "C" void kernel_launch(void* const* d_in, const int* in_sizes, int n_in,
                              void* d_out, int out_size) {
    const float* x   = (const float*)d_in[0];
    const float* gt  = (const float*)d_in[1];
    const float* gm  = (const float*)d_in[2];
    const float* isp = (const float*)d_in[3];
    const float* isd = (const float*)d_in[4];
    const float* isr = (const float*)d_in[5];
    const float* isl = (const float*)d_in[6];
    const float* tb  = (const float*)d_in[7];
    const float* tm  = (const float*)d_in[8];
    const int*   npt = (const int*)d_in[9];
    const float* t   = (const float*)d_in[10];
    float* out = (float*)d_out;

    fused_kernel<<<GRID, NT>>>(x, gt, gm, isp, isd, isr, isl, tm, npt, tb, t, out);
}